// round 14
// baseline (speedup 1.0000x reference)
#include <cuda_runtime.h>
#include <math.h>
#include <stdint.h>

#define NDIM 1152
#define WN   1408
#define NIC  384
#define NN_MAX 10000
#define NE_MAX 50000

// ---------------- static scratch (no allocation allowed) ----------------
__device__ float g_S0  [(size_t)NE_MAX * 512];
__device__ float g_H   [(size_t)NE_MAX * 128];   // es hidden
__device__ float g_HB  [(size_t)NE_MAX * 128];   // er hidden (concurrent)
__device__ float g_TPW [(size_t)NE_MAX * WN];
__device__ float g_XM  [(size_t)NN_MAX * NDIM];  // x permuted to m-major
__device__ float g_XP  [(size_t)NN_MAX * NDIM];  // m-major irrep layout
__device__ float g_F0  [(size_t)NE_MAX * NIC];
__device__ float g_H2  [(size_t)NE_MAX * NIC];
__device__ float g_G   [(size_t)NE_MAX * NIC];
__device__ float g_FIJ [(size_t)NE_MAX * NDIM];  // m-major (ungated)
__device__ float g_OUTM[(size_t)NE_MAX * NDIM];  // m-major
__device__ float g_W3J[363];

// ---------------- Wigner 3j init (exact port of reference) --------------
__constant__ int c_l1[11]  = {0,0,0,1,1,1,1,2,2,2,2};
__constant__ int c_l2[11]  = {0,1,2,0,1,1,2,0,1,2,2};
__constant__ int c_l3[11]  = {0,1,2,1,0,2,1,2,1,0,2};
__constant__ int c_off[11] = {0,1,10,35,44,53,98,143,168,213,238};

__device__ double dfact(int n){ double r=1.0; for(int i=2;i<=n;i++) r*=(double)i; return r; }

__device__ double su2cg(int j1,int j2,int j3,int m1,int m2,int m3){
    if (m1+m2 != m3) return 0.0;
    double pref = sqrt((2.0*j3+1.0)*dfact(j1+j2-j3)*dfact(j1-j2+j3)*dfact(-j1+j2+j3)/dfact(j1+j2+j3+1));
    pref *= sqrt(dfact(j3+m3)*dfact(j3-m3)*dfact(j1-m1)*dfact(j1+m1)*dfact(j2-m2)*dfact(j2+m2));
    double s = 0.0;
    for (int k=0;k<=j1+j2-j3;k++){
        int a=j1-m1-k, b=j2+m2-k, c=j3-j2+m1+k, d=j3-j1-m2+k;
        if (a<0||b<0||c<0||d<0) continue;
        double t = 1.0/(dfact(k)*dfact(j1+j2-j3-k)*dfact(a)*dfact(b)*dfact(c)*dfact(d));
        s += (k&1) ? -t : t;
    }
    return pref*s;
}

__device__ void qmat(int l, double* Qr, double* Qi){
    int d = 2*l+1;
    for (int i=0;i<d*d;i++){ Qr[i]=0.0; Qi[i]=0.0; }
    double is2 = 1.0/sqrt(2.0);
    for (int m=-l;m<0;m++){
        Qr[(l+m)*d+(l-m)] = is2;
        Qi[(l+m)*d+(l+m)] = -is2;
    }
    Qr[l*d+l] = 1.0;
    for (int m=1;m<=l;m++){
        double sg = (m&1) ? -1.0 : 1.0;
        Qr[(l+m)*d+(l+m)] = sg*is2;
        Qi[(l+m)*d+(l-m)] = sg*is2;
    }
    if (l==1){ for (int i=0;i<d*d;i++){ double r=Qr[i], im=Qi[i]; Qr[i]=im; Qi[i]=-r; } }
    else if (l==2){ for (int i=0;i<d*d;i++){ Qr[i]=-Qr[i]; Qi[i]=-Qi[i]; } }
}

__global__ void init_w3j_k(){
    int p = blockIdx.x;
    int l1=c_l1[p], l2=c_l2[p], l3=c_l3[p];
    int d1=2*l1+1, d2=2*l2+1, d3=2*l3+1;
    int n = d1*d2*d3;
    __shared__ double Cc[125];
    __shared__ double Q1r[25],Q1i[25],Q2r[25],Q2i[25],Q3r[25],Q3i[25];
    __shared__ double Tr[125], Ti[125];
    int tid = threadIdx.x;
    for (int idx=tid; idx<n; idx+=blockDim.x){
        int a = idx/(d2*d3), b = (idx/d3)%d2, c = idx%d3;
        Cc[idx] = su2cg(l1,l2,l3,a-l1,b-l2,c-l3);
    }
    if (tid==0){ qmat(l1,Q1r,Q1i); qmat(l2,Q2r,Q2i); qmat(l3,Q3r,Q3i); }
    __syncthreads();
    for (int idx=tid; idx<n; idx+=blockDim.x){
        int i = idx/(d2*d3), j = (idx/d3)%d2, k = idx%d3;
        double tre=0.0, tim=0.0;
        for (int a=0;a<d1;a++)
        for (int b=0;b<d2;b++){
            double q1r=Q1r[a*d1+i], q1i=Q1i[a*d1+i];
            double q2r=Q2r[b*d2+j], q2i=Q2i[b*d2+j];
            double q12r = q1r*q2r - q1i*q2i;
            double q12i = q1r*q2i + q1i*q2r;
            for (int c=0;c<d3;c++){
                double cc = Cc[(a*d2+b)*d3+c];
                if (cc==0.0) continue;
                double q3r = Q3r[c*d3+k], q3i = -Q3i[c*d3+k];
                tre += cc*(q12r*q3r - q12i*q3i);
                tim += cc*(q12r*q3i + q12i*q3r);
            }
        }
        Tr[idx]=tre; Ti[idx]=tim;
    }
    __syncthreads();
    if (tid==0){
        double nr=0.0, ni=0.0;
        for (int idx=0;idx<n;idx++){ nr += Tr[idx]*Tr[idx]; ni += Ti[idx]*Ti[idx]; }
        bool ure = (nr >= ni);
        double nn = sqrt(ure ? nr : ni);
        for (int idx=0;idx<n;idx++)
            g_W3J[c_off[p]+idx] = (float)((ure ? Tr[idx] : Ti[idx]) / nn);
    }
}

// ---------------- packed f32x2 helpers -----------------------------------
__device__ __forceinline__ unsigned long long pk2(float lo, float hi){
    unsigned long long r;
    asm("mov.b64 %0, {%1,%2};" : "=l"(r) : "f"(lo), "f"(hi));
    return r;
}
__device__ __forceinline__ void upk2(unsigned long long v, float& lo, float& hi){
    asm("mov.b64 {%0,%1}, %2;" : "=f"(lo), "=f"(hi) : "l"(v));
}
__device__ __forceinline__ unsigned long long ffma2(unsigned long long a,
                                                    unsigned long long b,
                                                    unsigned long long c){
    unsigned long long d;
    asm("fma.rn.f32x2 %0, %1, %2, %3;" : "=l"(d) : "l"(a), "l"(b), "l"(c));
    return d;
}

// ---------------- tiled SGEMM (16-wide k-chunks) -------------------------
// C = epi(alpha*A@B + bias [, *C]).  A row-major (ldaR, contiguous k),
// B row-major K x N (ldb), C row-major (ldcR, col stride 1), N mult of 128.
// Warp tile 32x64 (split 4+4 microtile).  EPI: 0 linear, 1 silu, 2 mult-into-C.
// GATED: A multiplied by Gm[row, goff+k] during staging.
template<int EPI, int GATED>
__global__ __launch_bounds__(256)
void sgemm_k(const float* __restrict__ A, int ldaR,
             const float* __restrict__ B, int ldb,
             float* __restrict__ C, long long ldcR,
             const float* __restrict__ bias, float alpha,
             int M, int N, int K, int zA, int zC,
             const float* __restrict__ Gm, int goff)
{
    __shared__ float As[2][16][132];
    __shared__ float Bs[2][16][132];
    const int bm = blockIdx.y * 128;
    const int bn = blockIdx.x * 128;
    A += (size_t)blockIdx.z * zA;
    C += (size_t)blockIdx.z * zC;
    const int tid  = threadIdx.x;
    const int lane = tid & 31, warp = tid >> 5;
    const int lx = lane & 7,  ly = lane >> 3;
    const int wx = warp & 1,  wy = warp >> 1;
    const int cb = (wx*8 + lx) * 4;
    const int rb = (wy*4 + ly) * 4;
    // staging maps (conflict-free STS)
    const int ar = tid & 127;            // A row in tile (0..127)
    const int ak = (tid >> 7) * 8;       // A k offset (0 or 8)
    const int bk = tid >> 4;             // B k row (0..15)
    const int bj = (tid & 15) * 8;       // B col offset (0..120)

    unsigned long long acc[8][4];
#pragma unroll
    for (int r=0;r<8;r++)
#pragma unroll
        for (int c=0;c<4;c++) acc[r][c] = pk2(0.f, 0.f);

    const int nc = (K+15)/16;
    float av[8], bv[8];

    // ---- load chunk 0 into av/bv ----
    {
        int gar = bm+ar, gk = ak;
#pragma unroll
        for (int i=0;i<8;i++) av[i] = 0.f;
        if (gar < M){
            const float* ap = A + (size_t)gar*ldaR;
            if (gk+7 < K){
                float4 t0 = *(const float4*)(ap+gk);
                float4 t1 = *(const float4*)(ap+gk+4);
                av[0]=t0.x; av[1]=t0.y; av[2]=t0.z; av[3]=t0.w;
                av[4]=t1.x; av[5]=t1.y; av[6]=t1.z; av[7]=t1.w;
            } else {
#pragma unroll
                for (int i=0;i<8;i++) if (gk+i < K) av[i] = ap[gk+i];
            }
            if (GATED){
                const float* gp = Gm + (size_t)gar*NIC + goff + gk;
                if (gk+7 < K){
                    float4 g0 = *(const float4*)gp, g1 = *(const float4*)(gp+4);
                    av[0]*=g0.x; av[1]*=g0.y; av[2]*=g0.z; av[3]*=g0.w;
                    av[4]*=g1.x; av[5]*=g1.y; av[6]*=g1.z; av[7]*=g1.w;
                } else {
#pragma unroll
                    for (int i=0;i<8;i++) if (gk+i < K) av[i] *= gp[i];
                }
            }
        }
#pragma unroll
        for (int i=0;i<8;i++) bv[i] = 0.f;
        if (bk < K){
            const float* bp = B + (size_t)bk*ldb + bn + bj;
            float4 t0 = *(const float4*)bp, t1 = *(const float4*)(bp+4);
            bv[0]=t0.x; bv[1]=t0.y; bv[2]=t0.z; bv[3]=t0.w;
            bv[4]=t1.x; bv[5]=t1.y; bv[6]=t1.z; bv[7]=t1.w;
        }
    }
    {
#pragma unroll
        for (int i=0;i<8;i++) As[0][ak+i][ar] = av[i];
        *(float4*)&Bs[0][bk][bj]   = make_float4(bv[0],bv[1],bv[2],bv[3]);
        *(float4*)&Bs[0][bk][bj+4] = make_float4(bv[4],bv[5],bv[6],bv[7]);
    }
    __syncthreads();

    for (int c=0; c<nc; c++){
        int cur = c & 1;
        // prefetch next chunk into registers
        if (c+1 < nc){
            int k0 = (c+1)*16;
            int gar = bm+ar, gk = k0+ak;
#pragma unroll
            for (int i=0;i<8;i++) av[i] = 0.f;
            if (gar < M){
                const float* ap = A + (size_t)gar*ldaR;
                if (gk+7 < K){
                    float4 t0 = *(const float4*)(ap+gk);
                    float4 t1 = *(const float4*)(ap+gk+4);
                    av[0]=t0.x; av[1]=t0.y; av[2]=t0.z; av[3]=t0.w;
                    av[4]=t1.x; av[5]=t1.y; av[6]=t1.z; av[7]=t1.w;
                } else {
#pragma unroll
                    for (int i=0;i<8;i++) if (gk+i < K) av[i] = ap[gk+i];
                }
                if (GATED){
                    const float* gp = Gm + (size_t)gar*NIC + goff + gk;
                    if (gk+7 < K){
                        float4 g0 = *(const float4*)gp, g1 = *(const float4*)(gp+4);
                        av[0]*=g0.x; av[1]*=g0.y; av[2]*=g0.z; av[3]*=g0.w;
                        av[4]*=g1.x; av[5]*=g1.y; av[6]*=g1.z; av[7]*=g1.w;
                    } else {
#pragma unroll
                        for (int i=0;i<8;i++) if (gk+i < K) av[i] *= gp[i];
                    }
                }
            }
#pragma unroll
            for (int i=0;i<8;i++) bv[i] = 0.f;
            int gbk = k0+bk;
            if (gbk < K){
                const float* bp = B + (size_t)gbk*ldb + bn + bj;
                float4 t0 = *(const float4*)bp, t1 = *(const float4*)(bp+4);
                bv[0]=t0.x; bv[1]=t0.y; bv[2]=t0.z; bv[3]=t0.w;
                bv[4]=t1.x; bv[5]=t1.y; bv[6]=t1.z; bv[7]=t1.w;
            }
        }
        // compute on current buffer
#pragma unroll
        for (int k=0;k<16;k++){
            float4 a0 = *(const float4*)&As[cur][k][rb];
            float4 a1 = *(const float4*)&As[cur][k][rb+64];
            ulonglong2 u0 = *(const ulonglong2*)&Bs[cur][k][cb];
            ulonglong2 u1 = *(const ulonglong2*)&Bs[cur][k][cb+64];
            unsigned long long b2[4] = {u0.x, u0.y, u1.x, u1.y};
            float aw[8] = {a0.x,a0.y,a0.z,a0.w,a1.x,a1.y,a1.z,a1.w};
#pragma unroll
            for (int r=0;r<8;r++){
                unsigned long long a2 = pk2(aw[r], aw[r]);
#pragma unroll
                for (int cc=0;cc<4;cc++)
                    acc[r][cc] = ffma2(a2, b2[cc], acc[r][cc]);
            }
        }
        // stage next buffer
        if (c+1 < nc){
            int nxt = (c+1)&1;
#pragma unroll
            for (int i=0;i<8;i++) As[nxt][ak+i][ar] = av[i];
            *(float4*)&Bs[nxt][bk][bj]   = make_float4(bv[0],bv[1],bv[2],bv[3]);
            *(float4*)&Bs[nxt][bk][bj+4] = make_float4(bv[4],bv[5],bv[6],bv[7]);
            __syncthreads();
        }
    }

    float bi[8];
#pragma unroll
    for (int c=0;c<8;c++){
        int gj = bn + cb + (c>>2)*64 + (c&3);
        bi[c] = bias ? bias[gj] : 0.f;
    }
#pragma unroll
    for (int r=0;r<8;r++){
        int gi = bm + rb + (r>>2)*64 + (r&3);
        if (gi >= M) continue;
        float v[8];
#pragma unroll
        for (int c=0;c<4;c++) upk2(acc[r][c], v[c*2], v[c*2+1]);
        float* cp0 = C + (long long)gi*ldcR + bn + cb;
        float* cp1 = cp0 + 64;
        if (EPI==2){
            float4 c0 = *(const float4*)cp0;
            float4 c1 = *(const float4*)cp1;
            float cv[8] = {c0.x,c0.y,c0.z,c0.w,c1.x,c1.y,c1.z,c1.w};
#pragma unroll
            for (int c=0;c<8;c++) v[c] = (v[c]*alpha + bi[c]) * cv[c];
        } else {
#pragma unroll
            for (int c=0;c<8;c++){
                float t = v[c]*alpha + bi[c];
                if (EPI==1) t = t / (1.f + __expf(-t));
                v[c] = t;
            }
        }
        *(float4*)cp0 = make_float4(v[0],v[1],v[2],v[3]);
        *(float4*)cp1 = make_float4(v[4],v[5],v[6],v[7]);
    }
}

// ---------------- glue kernels (m-major irrep layout) --------------------
__global__ void edge_s0_k(const float* __restrict__ x, const int* __restrict__ ei,
                          float* __restrict__ S0, int nE){
    int e = blockIdx.x, u = threadIdx.x;
    int s = ei[e], d = ei[nE+e];
    const float* a = x + (size_t)s*NDIM;
    const float* b = x + (size_t)d*NDIM;
    float* o = S0 + (size_t)e*512;
    o[u]      = a[u];
    o[128+u]  = b[u];
    float d1 = 0.f;
#pragma unroll
    for (int m=0;m<3;m++) d1 += a[128+u*3+m]*b[128+u*3+m];
    float d2 = 0.f;
#pragma unroll
    for (int m=0;m<5;m++) d2 += a[512+u*5+m]*b[512+u*5+m];
    o[256+u] = d1*0.57735026918962576f;
    o[384+u] = d2*0.44721359549995794f;
}

// u-major x -> m-major XM
__global__ void permute_in_k(const float* __restrict__ x, float* __restrict__ XM){
    __shared__ float buf[NDIM];
    int n = blockIdx.x, t = threadIdx.x;
    const float* src = x + (size_t)n*NDIM;
    for (int j=t;j<NDIM;j+=128) buf[j] = src[j];
    __syncthreads();
    float* o = XM + (size_t)n*NDIM;
    for (int j=t;j<NDIM;j+=128){
        float v;
        if (j < 128) v = buf[j];
        else if (j < 512){ int r=j-128; int m=r>>7, u=r&127; v = buf[128 + u*3 + m]; }
        else             { int r=j-512; int m=r/128, u=r%128; v = buf[512 + u*5 + m]; }
        o[j] = v;
    }
}

__global__ void f0_prep_k(const float* __restrict__ V, float* __restrict__ F0){
    int n = blockIdx.x, u = threadIdx.x;
    const float* r = V + (size_t)n*NDIM;
    float* o = F0 + (size_t)n*NIC;
    o[u] = r[u];
    float s = 0.f;
#pragma unroll
    for (int m=0;m<3;m++){ float t = r[128+m*128+u]; s += t*t; }
    o[128+u] = sqrtf(s);
    s = 0.f;
#pragma unroll
    for (int m=0;m<5;m++){ float t = r[512+m*128+u]; s += t*t; }
    o[256+u] = sqrtf(s);
}

__global__ void gate_k(float* __restrict__ V, const float* __restrict__ G){
    int n = blockIdx.x, u = threadIdx.x;
    float* r = V + (size_t)n*NDIM;
    const float* g = G + (size_t)n*NIC;
    r[u] = g[u];
    float g1 = g[128+u];
#pragma unroll
    for (int m=0;m<3;m++) r[128+m*128+u] *= g1;
    float g2 = g[256+u];
#pragma unroll
    for (int m=0;m<5;m++) r[512+m*128+u] *= g2;
}

// m-major tensor product; also emits F0 = [o0, |o1|, |o2|]
__global__ void tp_k(const float* __restrict__ XP, const int* __restrict__ ei,
                     const float* __restrict__ TPW, float* __restrict__ FIJ,
                     float* __restrict__ F0, int nE){
    __shared__ float w3[363];
    int e = blockIdx.x, u = threadIdx.x;
    for (int i=u;i<363;i+=128) w3[i] = g_W3J[i];
    __syncthreads();
    int s = ei[e], d = ei[nE+e];
    const float* a = XP + (size_t)s*NDIM;
    const float* b = XP + (size_t)d*NDIM;
    float s1 = a[u], s2 = b[u];
    float v11[3], v12[3], v21[5], v22[5];
#pragma unroll
    for (int m=0;m<3;m++){ v11[m]=a[128+m*128+u]; v12[m]=b[128+m*128+u]; }
#pragma unroll
    for (int m=0;m<5;m++){ v21[m]=a[512+m*128+u]; v22[m]=b[512+m*128+u]; }
    const float* W = TPW + (size_t)e*WN + u;
    const float PW0 = 0.57735026918962576f;
    const float PW1 = 0.86602540378443865f;
    const float PW2 = 1.11803398874989485f;
    float o0 = 0.f, o1[3] = {0,0,0}, o2[5] = {0,0,0,0,0};
    float wp, f, t;

    wp = W[0];
    o0 += PW0*wp*s1*s2*w3[0];
    wp = W[128]; f = PW1*wp*s1;
#pragma unroll
    for (int j=0;j<3;j++){ t = f*v12[j];
#pragma unroll
        for (int k=0;k<3;k++) o1[k] += t*w3[1 + j*3 + k]; }
    wp = W[256]; f = PW2*wp*s1;
#pragma unroll
    for (int j=0;j<5;j++){ t = f*v22[j];
#pragma unroll
        for (int k=0;k<5;k++) o2[k] += t*w3[10 + j*5 + k]; }
    wp = W[384]; f = PW1*wp*s2;
#pragma unroll
    for (int i=0;i<3;i++){ t = f*v11[i];
#pragma unroll
        for (int k=0;k<3;k++) o1[k] += t*w3[35 + i*3 + k]; }
    wp = W[512]; f = PW0*wp;
#pragma unroll
    for (int i=0;i<3;i++)
#pragma unroll
        for (int j=0;j<3;j++) o0 += f*v11[i]*v12[j]*w3[44 + i*3 + j];
    wp = W[640]; f = PW2*wp;
#pragma unroll
    for (int i=0;i<3;i++)
#pragma unroll
        for (int j=0;j<3;j++){ t = f*v11[i]*v12[j];
#pragma unroll
            for (int k=0;k<5;k++) o2[k] += t*w3[53 + (i*3+j)*5 + k]; }
    wp = W[768]; f = PW1*wp;
#pragma unroll
    for (int i=0;i<3;i++)
#pragma unroll
        for (int j=0;j<5;j++){ t = f*v11[i]*v22[j];
#pragma unroll
            for (int k=0;k<3;k++) o1[k] += t*w3[98 + (i*5+j)*3 + k]; }
    wp = W[896]; f = PW2*wp*s2;
#pragma unroll
    for (int i=0;i<5;i++){ t = f*v21[i];
#pragma unroll
        for (int k=0;k<5;k++) o2[k] += t*w3[143 + i*5 + k]; }
    wp = W[1024]; f = PW1*wp;
#pragma unroll
    for (int i=0;i<5;i++)
#pragma unroll
        for (int j=0;j<3;j++){ t = f*v21[i]*v12[j];
#pragma unroll
            for (int k=0;k<3;k++) o1[k] += t*w3[168 + (i*3+j)*3 + k]; }
    wp = W[1152]; f = PW0*wp;
#pragma unroll
    for (int i=0;i<5;i++)
#pragma unroll
        for (int j=0;j<5;j++) o0 += f*v21[i]*v22[j]*w3[213 + i*5 + j];
    wp = W[1280]; f = PW2*wp;
#pragma unroll
    for (int i=0;i<5;i++)
#pragma unroll
        for (int j=0;j<5;j++){ t = f*v21[i]*v22[j];
#pragma unroll
            for (int k=0;k<5;k++) o2[k] += t*w3[238 + (i*5+j)*5 + k]; }

    float* o = FIJ + (size_t)e*NDIM;
    o[u] = o0;
    float n1 = 0.f, n2 = 0.f;
#pragma unroll
    for (int m=0;m<3;m++){ o[128+m*128+u] = o1[m]; n1 += o1[m]*o1[m]; }
#pragma unroll
    for (int m=0;m<5;m++){ o[512+m*128+u] = o2[m]; n2 += o2[m]*o2[m]; }
    float* fo = F0 + (size_t)e*NIC;
    fo[u]       = o0;
    fo[128+u]   = sqrtf(n1);
    fo[256+u]   = sqrtf(n2);
}

// m-major -> reference u-major interleave
__global__ void permute_out_k(const float* __restrict__ OM, float* __restrict__ out){
    __shared__ float buf[NDIM];
    int e = blockIdx.x, t = threadIdx.x;
    const float* src = OM + (size_t)e*NDIM;
    for (int j=t;j<NDIM;j+=128) buf[j] = src[j];
    __syncthreads();
    float* o = out + (size_t)e*NDIM;
    for (int j=t;j<NDIM;j+=128){
        float v;
        if (j < 128) v = buf[j];
        else if (j < 512){ int r=j-128; v = buf[128 + (r%3)*128 + r/3]; }
        else             { int r=j-512; v = buf[512 + (r%5)*128 + r/5]; }
        o[j] = v;
    }
}

// ---------------- launch --------------------------------------------------
static inline int cdiv(int a, int b){ return (a+b-1)/b; }

extern "C" void kernel_launch(void* const* d_in, const int* in_sizes, int n_in,
                              void* d_out, int out_size)
{
    const float* x     = (const float*)d_in[0];
    const float* ea    = (const float*)d_in[1];
    const int*   ei    = (const int*)  d_in[2];
    const float* Wp0   = (const float*)d_in[3];
    const float* Wp1   = (const float*)d_in[4];
    const float* Wp2   = (const float*)d_in[5];
    const float* bp0   = (const float*)d_in[6];
    const float* ngAW1 = (const float*)d_in[7];
    const float* ngAb1 = (const float*)d_in[8];
    const float* ngAW2 = (const float*)d_in[9];
    const float* ngAb2 = (const float*)d_in[10];
    const float* esW1  = (const float*)d_in[11];
    const float* esb1  = (const float*)d_in[12];
    const float* esW2  = (const float*)d_in[13];
    const float* esb2  = (const float*)d_in[14];
    const float* erW1  = (const float*)d_in[15];
    const float* erb1  = (const float*)d_in[16];
    const float* erW2  = (const float*)d_in[17];
    const float* erb2  = (const float*)d_in[18];
    const float* ngBW1 = (const float*)d_in[19];
    const float* ngBb1 = (const float*)d_in[20];
    const float* ngBW2 = (const float*)d_in[21];
    const float* ngBb2 = (const float*)d_in[22];
    const float* Wq0   = (const float*)d_in[23];
    const float* Wq1   = (const float*)d_in[24];
    const float* Wq2   = (const float*)d_in[25];
    float* out = (float*)d_out;

    int nN = in_sizes[0] / NDIM;
    int nE = in_sizes[2] / 2;
    int rtE = cdiv(nE,128), rtN = cdiv(nN,128);

    float *S0,*H,*HB,*TPW,*XM,*XP,*F0,*H2,*G,*FIJ,*OUTM;
    cudaGetSymbolAddress((void**)&S0,  g_S0);
    cudaGetSymbolAddress((void**)&H,   g_H);
    cudaGetSymbolAddress((void**)&HB,  g_HB);
    cudaGetSymbolAddress((void**)&TPW, g_TPW);
    cudaGetSymbolAddress((void**)&XM,  g_XM);
    cudaGetSymbolAddress((void**)&XP,  g_XP);
    cudaGetSymbolAddress((void**)&F0,  g_F0);
    cudaGetSymbolAddress((void**)&H2,  g_H2);
    cudaGetSymbolAddress((void**)&G,   g_G);
    cudaGetSymbolAddress((void**)&FIJ, g_FIJ);
    cudaGetSymbolAddress((void**)&OUTM,g_OUTM);

    const float inv = 0.08838834764831845f;   // 1/sqrt(128)
    dim3 thr(256);
    const float* NOB = (const float*)0;
    const float* NOG = (const float*)0;

    // lazily created side streams + fork/join events
    static cudaStream_t s1 = 0, s2 = 0;
    static cudaEvent_t evR = 0, evEr = 0, evNode = 0;
    if (!s1){
        cudaStreamCreateWithFlags(&s1, cudaStreamNonBlocking);
        cudaStreamCreateWithFlags(&s2, cudaStreamNonBlocking);
        cudaEventCreateWithFlags(&evR,   cudaEventDisableTiming);
        cudaEventCreateWithFlags(&evEr,  cudaEventDisableTiming);
        cudaEventCreateWithFlags(&evNode,cudaEventDisableTiming);
    }

    // ---- fork ----
    cudaEventRecord(evR, 0);
    cudaStreamWaitEvent(s1, evR, 0);
    cudaStreamWaitEvent(s2, evR, 0);

    // s1: er branch  (HB = silu(ea@erW1+b1); TPW = HB@erW2 + b2)
    sgemm_k<1,0><<<dim3(1,rtE,1),  thr, 0, s1>>>(ea,  20, erW1, 128, HB, 128, erb1, 1.f, nE, 128, 20, 0,0, NOG,0);
    sgemm_k<0,0><<<dim3(11,rtE,1), thr, 0, s1>>>(HB, 128, erW2, WN, TPW, WN,  erb2, 1.f, nE, WN, 128, 0,0, NOG,0);
    cudaEventRecord(evEr, s1);

    // s2: w3j + node chain (independent of edges until tp_k)
    init_w3j_k<<<11,128,0,s2>>>();
    permute_in_k<<<nN,128,0,s2>>>(x, XM);
    sgemm_k<0,0><<<dim3(1,rtN,1), thr,0,s2>>>(XM,     NDIM, Wp0, 128, XP,     NDIM, bp0, inv, nN, 128, 128, 0,   0,   NOG,0);
    sgemm_k<0,0><<<dim3(1,rtN,3), thr,0,s2>>>(XM+128, NDIM, Wp1, 128, XP+128, NDIM, NOB, inv, nN, 128, 128, 128, 128, NOG,0);
    sgemm_k<0,0><<<dim3(1,rtN,5), thr,0,s2>>>(XM+512, NDIM, Wp2, 128, XP+512, NDIM, NOB, inv, nN, 128, 128, 128, 128, NOG,0);
    f0_prep_k<<<nN,128,0,s2>>>(XP, F0);
    sgemm_k<1,0><<<dim3(3,rtN,1), thr,0,s2>>>(F0, NIC, ngAW1, NIC, H2, NIC, ngAb1, 1.f, nN, NIC, NIC, 0,0, NOG,0);
    sgemm_k<0,0><<<dim3(3,rtN,1), thr,0,s2>>>(H2, NIC, ngAW2, NIC, G,  NIC, ngAb2, 1.f, nN, NIC, NIC, 0,0, NOG,0);
    gate_k<<<nN,128,0,s2>>>(XP, G);
    cudaEventRecord(evNode, s2);

    // stream 0: es branch
    edge_s0_k<<<nE,128>>>(x, ei, S0, nE);
    sgemm_k<1,0><<<dim3(1,rtE,1),  thr>>>(S0, 512, esW1, 128, H, 128, esb1, 1.f, nE, 128, 512, 0,0, NOG,0);
    cudaStreamWaitEvent(0, evEr, 0);            // join er chain
    sgemm_k<2,0><<<dim3(11,rtE,1), thr>>>(H, 128, esW2, WN, TPW, WN, esb2, 1.f, nE, WN, 128, 0,0, NOG,0);

    // join node chain, then tensor product per edge (also emits F0)
    cudaStreamWaitEvent(0, evNode, 0);
    tp_k<<<nE,128>>>(XP, ei, TPW, FIJ, F0, nE);

    // edge post: norm_gate MLP (gate G; applied via fusion below)
    sgemm_k<1,0><<<dim3(3,rtE,1), thr>>>(F0, NIC, ngBW1, NIC, H2, NIC, ngBb1, 1.f, nE, NIC, NIC, 0,0, NOG,0);
    sgemm_k<0,0><<<dim3(3,rtE,1), thr>>>(H2, NIC, ngBW2, NIC, G,  NIC, ngBb2, 1.f, nE, NIC, NIC, 0,0, NOG,0);

    // edge post: o3_linear -> OUTM (m-major); gate fused into A-staging.
    sgemm_k<0,0><<<dim3(1,rtE,1), thr>>>(G,       NIC,  Wq0, 128, OUTM,     NDIM, NOB, inv, nE, 128, 128, 0,   0,   NOG, 0);
    sgemm_k<0,1><<<dim3(1,rtE,3), thr>>>(FIJ+128, NDIM, Wq1, 128, OUTM+128, NDIM, NOB, inv, nE, 128, 128, 128, 128, G, 128);
    sgemm_k<0,1><<<dim3(1,rtE,5), thr>>>(FIJ+512, NDIM, Wq2, 128, OUTM+512, NDIM, NOB, inv, nE, 128, 128, 128, 128, G, 256);

    // interleave to reference layout
    permute_out_k<<<nE,128>>>(OUTM, out);
}

// round 15
// speedup vs baseline: 1.1876x; 1.1876x over previous
#include <cuda_runtime.h>
#include <math.h>
#include <stdint.h>

#define NDIM 1152
#define WN   1408
#define NIC  384
#define NN_MAX 10000
#define NE_MAX 50000

// ---------------- static scratch (no allocation allowed) ----------------
__device__ float g_S0  [(size_t)NE_MAX * 512];
__device__ float g_H   [(size_t)NE_MAX * 128];   // es hidden
__device__ float g_HB  [(size_t)NE_MAX * 128];   // er hidden (concurrent)
__device__ float g_TPW [(size_t)NE_MAX * WN];
__device__ float g_XM  [(size_t)NN_MAX * NDIM];  // x permuted to m-major
__device__ float g_XP  [(size_t)NN_MAX * NDIM];  // m-major irrep layout
__device__ float g_F0  [(size_t)NE_MAX * NIC];
__device__ float g_H2  [(size_t)NE_MAX * NIC];
__device__ float g_G   [(size_t)NE_MAX * NIC];
__device__ float g_FIJ [(size_t)NE_MAX * NDIM];  // m-major (ungated)
__device__ float g_OUTM[(size_t)NE_MAX * NDIM];  // m-major
__device__ float g_W3J[363];

// ---------------- Wigner 3j init (exact port of reference) --------------
__constant__ int c_l1[11]  = {0,0,0,1,1,1,1,2,2,2,2};
__constant__ int c_l2[11]  = {0,1,2,0,1,1,2,0,1,2,2};
__constant__ int c_l3[11]  = {0,1,2,1,0,2,1,2,1,0,2};
__constant__ int c_off[11] = {0,1,10,35,44,53,98,143,168,213,238};

__device__ double dfact(int n){ double r=1.0; for(int i=2;i<=n;i++) r*=(double)i; return r; }

__device__ double su2cg(int j1,int j2,int j3,int m1,int m2,int m3){
    if (m1+m2 != m3) return 0.0;
    double pref = sqrt((2.0*j3+1.0)*dfact(j1+j2-j3)*dfact(j1-j2+j3)*dfact(-j1+j2+j3)/dfact(j1+j2+j3+1));
    pref *= sqrt(dfact(j3+m3)*dfact(j3-m3)*dfact(j1-m1)*dfact(j1+m1)*dfact(j2-m2)*dfact(j2+m2));
    double s = 0.0;
    for (int k=0;k<=j1+j2-j3;k++){
        int a=j1-m1-k, b=j2+m2-k, c=j3-j2+m1+k, d=j3-j1-m2+k;
        if (a<0||b<0||c<0||d<0) continue;
        double t = 1.0/(dfact(k)*dfact(j1+j2-j3-k)*dfact(a)*dfact(b)*dfact(c)*dfact(d));
        s += (k&1) ? -t : t;
    }
    return pref*s;
}

__device__ void qmat(int l, double* Qr, double* Qi){
    int d = 2*l+1;
    for (int i=0;i<d*d;i++){ Qr[i]=0.0; Qi[i]=0.0; }
    double is2 = 1.0/sqrt(2.0);
    for (int m=-l;m<0;m++){
        Qr[(l+m)*d+(l-m)] = is2;
        Qi[(l+m)*d+(l+m)] = -is2;
    }
    Qr[l*d+l] = 1.0;
    for (int m=1;m<=l;m++){
        double sg = (m&1) ? -1.0 : 1.0;
        Qr[(l+m)*d+(l+m)] = sg*is2;
        Qi[(l+m)*d+(l-m)] = sg*is2;
    }
    if (l==1){ for (int i=0;i<d*d;i++){ double r=Qr[i], im=Qi[i]; Qr[i]=im; Qi[i]=-r; } }
    else if (l==2){ for (int i=0;i<d*d;i++){ Qr[i]=-Qr[i]; Qi[i]=-Qi[i]; } }
}

__global__ void init_w3j_k(){
    int p = blockIdx.x;
    int l1=c_l1[p], l2=c_l2[p], l3=c_l3[p];
    int d1=2*l1+1, d2=2*l2+1, d3=2*l3+1;
    int n = d1*d2*d3;
    __shared__ double Cc[125];
    __shared__ double Q1r[25],Q1i[25],Q2r[25],Q2i[25],Q3r[25],Q3i[25];
    __shared__ double Tr[125], Ti[125];
    int tid = threadIdx.x;
    for (int idx=tid; idx<n; idx+=blockDim.x){
        int a = idx/(d2*d3), b = (idx/d3)%d2, c = idx%d3;
        Cc[idx] = su2cg(l1,l2,l3,a-l1,b-l2,c-l3);
    }
    if (tid==0){ qmat(l1,Q1r,Q1i); qmat(l2,Q2r,Q2i); qmat(l3,Q3r,Q3i); }
    __syncthreads();
    for (int idx=tid; idx<n; idx+=blockDim.x){
        int i = idx/(d2*d3), j = (idx/d3)%d2, k = idx%d3;
        double tre=0.0, tim=0.0;
        for (int a=0;a<d1;a++)
        for (int b=0;b<d2;b++){
            double q1r=Q1r[a*d1+i], q1i=Q1i[a*d1+i];
            double q2r=Q2r[b*d2+j], q2i=Q2i[b*d2+j];
            double q12r = q1r*q2r - q1i*q2i;
            double q12i = q1r*q2i + q1i*q2r;
            for (int c=0;c<d3;c++){
                double cc = Cc[(a*d2+b)*d3+c];
                if (cc==0.0) continue;
                double q3r = Q3r[c*d3+k], q3i = -Q3i[c*d3+k];
                tre += cc*(q12r*q3r - q12i*q3i);
                tim += cc*(q12r*q3i + q12i*q3r);
            }
        }
        Tr[idx]=tre; Ti[idx]=tim;
    }
    __syncthreads();
    if (tid==0){
        double nr=0.0, ni=0.0;
        for (int idx=0;idx<n;idx++){ nr += Tr[idx]*Tr[idx]; ni += Ti[idx]*Ti[idx]; }
        bool ure = (nr >= ni);
        double nn = sqrt(ure ? nr : ni);
        for (int idx=0;idx<n;idx++)
            g_W3J[c_off[p]+idx] = (float)((ure ? Tr[idx] : Ti[idx]) / nn);
    }
}

// ---------------- packed f32x2 helpers -----------------------------------
__device__ __forceinline__ unsigned long long pk2(float lo, float hi){
    unsigned long long r;
    asm("mov.b64 %0, {%1,%2};" : "=l"(r) : "f"(lo), "f"(hi));
    return r;
}
__device__ __forceinline__ void upk2(unsigned long long v, float& lo, float& hi){
    asm("mov.b64 {%0,%1}, %2;" : "=f"(lo), "=f"(hi) : "l"(v));
}
__device__ __forceinline__ unsigned long long ffma2(unsigned long long a,
                                                    unsigned long long b,
                                                    unsigned long long c){
    unsigned long long d;
    asm("fma.rn.f32x2 %0, %1, %2, %3;" : "=l"(d) : "l"(a), "l"(b), "l"(c));
    return d;
}

// ---------------- tiled SGEMM (proven R12 engine: 8-wide k-chunks) -------
// C = epi(alpha*A@B + bias [, *C]).  A row-major (ldaR, contiguous k),
// B row-major K x N (ldb), C row-major (ldcR, col stride 1), N mult of 128.
// Warp tile 32x64 (split 4+4 microtile).  EPI: 0 linear, 1 silu, 2 mult-into-C.
// GATED: A multiplied by Gm[row, goff+k] during staging.
template<int EPI, int GATED>
__global__ __launch_bounds__(256)
void sgemm_k(const float* __restrict__ A, int ldaR,
             const float* __restrict__ B, int ldb,
             float* __restrict__ C, long long ldcR,
             const float* __restrict__ bias, float alpha,
             int M, int N, int K, int zA, int zC,
             const float* __restrict__ Gm, int goff)
{
    __shared__ float As[2][8][132];
    __shared__ float Bs[2][8][132];
    const int bm = blockIdx.y * 128;
    const int bn = blockIdx.x * 128;
    A += (size_t)blockIdx.z * zA;
    C += (size_t)blockIdx.z * zC;
    const int tid  = threadIdx.x;
    const int lane = tid & 31, warp = tid >> 5;
    const int lx = lane & 7,  ly = lane >> 3;
    const int wx = warp & 1,  wy = warp >> 1;
    const int cb = (wx*8 + lx) * 4;
    const int rb = (wy*4 + ly) * 4;
    const int ar = tid >> 1;
    const int ak = (tid & 1) * 4;
    const int bk = tid >> 5;
    const int bj = (tid & 31) * 4;

    unsigned long long acc[8][4];
#pragma unroll
    for (int r=0;r<8;r++)
#pragma unroll
        for (int c=0;c<4;c++) acc[r][c] = pk2(0.f, 0.f);

    const int nc = (K+7)/8;
    float4 va, vb;

    {
        int gar = bm+ar, gk = ak;
        va = make_float4(0.f,0.f,0.f,0.f);
        if (gar < M){
            const float* ap = A + (size_t)gar*ldaR;
            if (gk+3 < K) va = *(const float4*)(ap+gk);
            else {
                if (gk   < K) va.x = ap[gk];
                if (gk+1 < K) va.y = ap[gk+1];
                if (gk+2 < K) va.z = ap[gk+2];
                if (gk+3 < K) va.w = ap[gk+3];
            }
            if (GATED){
                float4 vg = *(const float4*)(Gm + (size_t)gar*NIC + goff + gk);
                va.x *= vg.x; va.y *= vg.y; va.z *= vg.z; va.w *= vg.w;
            }
        }
        vb = make_float4(0.f,0.f,0.f,0.f);
        if (bk < K) vb = *(const float4*)(B + (size_t)bk*ldb + bn + bj);
    }
    As[0][ak  ][ar] = va.x;
    As[0][ak+1][ar] = va.y;
    As[0][ak+2][ar] = va.z;
    As[0][ak+3][ar] = va.w;
    *(float4*)&Bs[0][bk][bj] = vb;
    __syncthreads();

    for (int c=0; c<nc; c++){
        int cur = c & 1;
        if (c+1 < nc){
            int k0 = (c+1)*8;
            int gar = bm+ar, gk = k0+ak;
            va = make_float4(0.f,0.f,0.f,0.f);
            if (gar < M){
                const float* ap = A + (size_t)gar*ldaR;
                if (gk+3 < K) va = *(const float4*)(ap+gk);
                else {
                    if (gk   < K) va.x = ap[gk];
                    if (gk+1 < K) va.y = ap[gk+1];
                    if (gk+2 < K) va.z = ap[gk+2];
                    if (gk+3 < K) va.w = ap[gk+3];
                }
                if (GATED){
                    float4 vg = *(const float4*)(Gm + (size_t)gar*NIC + goff + gk);
                    va.x *= vg.x; va.y *= vg.y; va.z *= vg.z; va.w *= vg.w;
                }
            }
            vb = make_float4(0.f,0.f,0.f,0.f);
            int gbk = k0+bk;
            if (gbk < K) vb = *(const float4*)(B + (size_t)gbk*ldb + bn + bj);
        }
#pragma unroll
        for (int k=0;k<8;k++){
            float4 a0 = *(const float4*)&As[cur][k][rb];
            float4 a1 = *(const float4*)&As[cur][k][rb+64];
            ulonglong2 u0 = *(const ulonglong2*)&Bs[cur][k][cb];
            ulonglong2 u1 = *(const ulonglong2*)&Bs[cur][k][cb+64];
            unsigned long long b2[4] = {u0.x, u0.y, u1.x, u1.y};
            float av[8] = {a0.x,a0.y,a0.z,a0.w,a1.x,a1.y,a1.z,a1.w};
#pragma unroll
            for (int r=0;r<8;r++){
                unsigned long long a2 = pk2(av[r], av[r]);
#pragma unroll
                for (int cc=0;cc<4;cc++)
                    acc[r][cc] = ffma2(a2, b2[cc], acc[r][cc]);
            }
        }
        if (c+1 < nc){
            int nxt = (c+1)&1;
            As[nxt][ak  ][ar] = va.x;
            As[nxt][ak+1][ar] = va.y;
            As[nxt][ak+2][ar] = va.z;
            As[nxt][ak+3][ar] = va.w;
            *(float4*)&Bs[nxt][bk][bj] = vb;
            __syncthreads();
        }
    }

    float bi[8];
#pragma unroll
    for (int c=0;c<8;c++){
        int gj = bn + cb + (c>>2)*64 + (c&3);
        bi[c] = bias ? bias[gj] : 0.f;
    }
#pragma unroll
    for (int r=0;r<8;r++){
        int gi = bm + rb + (r>>2)*64 + (r&3);
        if (gi >= M) continue;
        float v[8];
#pragma unroll
        for (int c=0;c<4;c++) upk2(acc[r][c], v[c*2], v[c*2+1]);
        float* cp0 = C + (long long)gi*ldcR + bn + cb;
        float* cp1 = cp0 + 64;
        if (EPI==2){
            float4 c0 = *(const float4*)cp0;
            float4 c1 = *(const float4*)cp1;
            float cv[8] = {c0.x,c0.y,c0.z,c0.w,c1.x,c1.y,c1.z,c1.w};
#pragma unroll
            for (int c=0;c<8;c++) v[c] = (v[c]*alpha + bi[c]) * cv[c];
        } else {
#pragma unroll
            for (int c=0;c<8;c++){
                float t = v[c]*alpha + bi[c];
                if (EPI==1) t = t / (1.f + __expf(-t));
                v[c] = t;
            }
        }
        *(float4*)cp0 = make_float4(v[0],v[1],v[2],v[3]);
        *(float4*)cp1 = make_float4(v[4],v[5],v[6],v[7]);
    }
}

// ---------------- glue kernels (m-major irrep layout) --------------------
__global__ void edge_s0_k(const float* __restrict__ x, const int* __restrict__ ei,
                          float* __restrict__ S0, int nE){
    int e = blockIdx.x, u = threadIdx.x;
    int s = ei[e], d = ei[nE+e];
    const float* a = x + (size_t)s*NDIM;
    const float* b = x + (size_t)d*NDIM;
    float* o = S0 + (size_t)e*512;
    o[u]      = a[u];
    o[128+u]  = b[u];
    float d1 = 0.f;
#pragma unroll
    for (int m=0;m<3;m++) d1 += a[128+u*3+m]*b[128+u*3+m];
    float d2 = 0.f;
#pragma unroll
    for (int m=0;m<5;m++) d2 += a[512+u*5+m]*b[512+u*5+m];
    o[256+u] = d1*0.57735026918962576f;
    o[384+u] = d2*0.44721359549995794f;
}

// u-major x -> m-major XM
__global__ void permute_in_k(const float* __restrict__ x, float* __restrict__ XM){
    __shared__ float buf[NDIM];
    int n = blockIdx.x, t = threadIdx.x;
    const float* src = x + (size_t)n*NDIM;
    for (int j=t;j<NDIM;j+=128) buf[j] = src[j];
    __syncthreads();
    float* o = XM + (size_t)n*NDIM;
    for (int j=t;j<NDIM;j+=128){
        float v;
        if (j < 128) v = buf[j];
        else if (j < 512){ int r=j-128; int m=r>>7, u=r&127; v = buf[128 + u*3 + m]; }
        else             { int r=j-512; int m=r/128, u=r%128; v = buf[512 + u*5 + m]; }
        o[j] = v;
    }
}

__global__ void f0_prep_k(const float* __restrict__ V, float* __restrict__ F0){
    int n = blockIdx.x, u = threadIdx.x;
    const float* r = V + (size_t)n*NDIM;
    float* o = F0 + (size_t)n*NIC;
    o[u] = r[u];
    float s = 0.f;
#pragma unroll
    for (int m=0;m<3;m++){ float t = r[128+m*128+u]; s += t*t; }
    o[128+u] = sqrtf(s);
    s = 0.f;
#pragma unroll
    for (int m=0;m<5;m++){ float t = r[512+m*128+u]; s += t*t; }
    o[256+u] = sqrtf(s);
}

__global__ void gate_k(float* __restrict__ V, const float* __restrict__ G){
    int n = blockIdx.x, u = threadIdx.x;
    float* r = V + (size_t)n*NDIM;
    const float* g = G + (size_t)n*NIC;
    r[u] = g[u];
    float g1 = g[128+u];
#pragma unroll
    for (int m=0;m<3;m++) r[128+m*128+u] *= g1;
    float g2 = g[256+u];
#pragma unroll
    for (int m=0;m<5;m++) r[512+m*128+u] *= g2;
}

// m-major tensor product; also emits F0 = [o0, |o1|, |o2|]
__global__ void tp_k(const float* __restrict__ XP, const int* __restrict__ ei,
                     const float* __restrict__ TPW, float* __restrict__ FIJ,
                     float* __restrict__ F0, int nE){
    __shared__ float w3[363];
    int e = blockIdx.x, u = threadIdx.x;
    for (int i=u;i<363;i+=128) w3[i] = g_W3J[i];
    __syncthreads();
    int s = ei[e], d = ei[nE+e];
    const float* a = XP + (size_t)s*NDIM;
    const float* b = XP + (size_t)d*NDIM;
    float s1 = a[u], s2 = b[u];
    float v11[3], v12[3], v21[5], v22[5];
#pragma unroll
    for (int m=0;m<3;m++){ v11[m]=a[128+m*128+u]; v12[m]=b[128+m*128+u]; }
#pragma unroll
    for (int m=0;m<5;m++){ v21[m]=a[512+m*128+u]; v22[m]=b[512+m*128+u]; }
    const float* W = TPW + (size_t)e*WN + u;
    const float PW0 = 0.57735026918962576f;
    const float PW1 = 0.86602540378443865f;
    const float PW2 = 1.11803398874989485f;
    float o0 = 0.f, o1[3] = {0,0,0}, o2[5] = {0,0,0,0,0};
    float wp, f, t;

    wp = W[0];
    o0 += PW0*wp*s1*s2*w3[0];
    wp = W[128]; f = PW1*wp*s1;
#pragma unroll
    for (int j=0;j<3;j++){ t = f*v12[j];
#pragma unroll
        for (int k=0;k<3;k++) o1[k] += t*w3[1 + j*3 + k]; }
    wp = W[256]; f = PW2*wp*s1;
#pragma unroll
    for (int j=0;j<5;j++){ t = f*v22[j];
#pragma unroll
        for (int k=0;k<5;k++) o2[k] += t*w3[10 + j*5 + k]; }
    wp = W[384]; f = PW1*wp*s2;
#pragma unroll
    for (int i=0;i<3;i++){ t = f*v11[i];
#pragma unroll
        for (int k=0;k<3;k++) o1[k] += t*w3[35 + i*3 + k]; }
    wp = W[512]; f = PW0*wp;
#pragma unroll
    for (int i=0;i<3;i++)
#pragma unroll
        for (int j=0;j<3;j++) o0 += f*v11[i]*v12[j]*w3[44 + i*3 + j];
    wp = W[640]; f = PW2*wp;
#pragma unroll
    for (int i=0;i<3;i++)
#pragma unroll
        for (int j=0;j<3;j++){ t = f*v11[i]*v12[j];
#pragma unroll
            for (int k=0;k<5;k++) o2[k] += t*w3[53 + (i*3+j)*5 + k]; }
    wp = W[768]; f = PW1*wp;
#pragma unroll
    for (int i=0;i<3;i++)
#pragma unroll
        for (int j=0;j<5;j++){ t = f*v11[i]*v22[j];
#pragma unroll
            for (int k=0;k<3;k++) o1[k] += t*w3[98 + (i*5+j)*3 + k]; }
    wp = W[896]; f = PW2*wp*s2;
#pragma unroll
    for (int i=0;i<5;i++){ t = f*v21[i];
#pragma unroll
        for (int k=0;k<5;k++) o2[k] += t*w3[143 + i*5 + k]; }
    wp = W[1024]; f = PW1*wp;
#pragma unroll
    for (int i=0;i<5;i++)
#pragma unroll
        for (int j=0;j<3;j++){ t = f*v21[i]*v12[j];
#pragma unroll
            for (int k=0;k<3;k++) o1[k] += t*w3[168 + (i*3+j)*3 + k]; }
    wp = W[1152]; f = PW0*wp;
#pragma unroll
    for (int i=0;i<5;i++)
#pragma unroll
        for (int j=0;j<5;j++) o0 += f*v21[i]*v22[j]*w3[213 + i*5 + j];
    wp = W[1280]; f = PW2*wp;
#pragma unroll
    for (int i=0;i<5;i++)
#pragma unroll
        for (int j=0;j<5;j++){ t = f*v21[i]*v22[j];
#pragma unroll
            for (int k=0;k<5;k++) o2[k] += t*w3[238 + (i*5+j)*5 + k]; }

    float* o = FIJ + (size_t)e*NDIM;
    o[u] = o0;
    float n1 = 0.f, n2 = 0.f;
#pragma unroll
    for (int m=0;m<3;m++){ o[128+m*128+u] = o1[m]; n1 += o1[m]*o1[m]; }
#pragma unroll
    for (int m=0;m<5;m++){ o[512+m*128+u] = o2[m]; n2 += o2[m]*o2[m]; }
    float* fo = F0 + (size_t)e*NIC;
    fo[u]       = o0;
    fo[128+u]   = sqrtf(n1);
    fo[256+u]   = sqrtf(n2);
}

// m-major -> reference u-major interleave
__global__ void permute_out_k(const float* __restrict__ OM, float* __restrict__ out){
    __shared__ float buf[NDIM];
    int e = blockIdx.x, t = threadIdx.x;
    const float* src = OM + (size_t)e*NDIM;
    for (int j=t;j<NDIM;j+=128) buf[j] = src[j];
    __syncthreads();
    float* o = out + (size_t)e*NDIM;
    for (int j=t;j<NDIM;j+=128){
        float v;
        if (j < 128) v = buf[j];
        else if (j < 512){ int r=j-128; v = buf[128 + (r%3)*128 + r/3]; }
        else             { int r=j-512; v = buf[512 + (r%5)*128 + r/5]; }
        o[j] = v;
    }
}

// ---------------- launch --------------------------------------------------
static inline int cdiv(int a, int b){ return (a+b-1)/b; }

extern "C" void kernel_launch(void* const* d_in, const int* in_sizes, int n_in,
                              void* d_out, int out_size)
{
    const float* x     = (const float*)d_in[0];
    const float* ea    = (const float*)d_in[1];
    const int*   ei    = (const int*)  d_in[2];
    const float* Wp0   = (const float*)d_in[3];
    const float* Wp1   = (const float*)d_in[4];
    const float* Wp2   = (const float*)d_in[5];
    const float* bp0   = (const float*)d_in[6];
    const float* ngAW1 = (const float*)d_in[7];
    const float* ngAb1 = (const float*)d_in[8];
    const float* ngAW2 = (const float*)d_in[9];
    const float* ngAb2 = (const float*)d_in[10];
    const float* esW1  = (const float*)d_in[11];
    const float* esb1  = (const float*)d_in[12];
    const float* esW2  = (const float*)d_in[13];
    const float* esb2  = (const float*)d_in[14];
    const float* erW1  = (const float*)d_in[15];
    const float* erb1  = (const float*)d_in[16];
    const float* erW2  = (const float*)d_in[17];
    const float* erb2  = (const float*)d_in[18];
    const float* ngBW1 = (const float*)d_in[19];
    const float* ngBb1 = (const float*)d_in[20];
    const float* ngBW2 = (const float*)d_in[21];
    const float* ngBb2 = (const float*)d_in[22];
    const float* Wq0   = (const float*)d_in[23];
    const float* Wq1   = (const float*)d_in[24];
    const float* Wq2   = (const float*)d_in[25];
    float* out = (float*)d_out;

    int nN = in_sizes[0] / NDIM;
    int nE = in_sizes[2] / 2;
    int rtE = cdiv(nE,128), rtN = cdiv(nN,128);

    float *S0,*H,*HB,*TPW,*XM,*XP,*F0,*H2,*G,*FIJ,*OUTM;
    cudaGetSymbolAddress((void**)&S0,  g_S0);
    cudaGetSymbolAddress((void**)&H,   g_H);
    cudaGetSymbolAddress((void**)&HB,  g_HB);
    cudaGetSymbolAddress((void**)&TPW, g_TPW);
    cudaGetSymbolAddress((void**)&XM,  g_XM);
    cudaGetSymbolAddress((void**)&XP,  g_XP);
    cudaGetSymbolAddress((void**)&F0,  g_F0);
    cudaGetSymbolAddress((void**)&H2,  g_H2);
    cudaGetSymbolAddress((void**)&G,   g_G);
    cudaGetSymbolAddress((void**)&FIJ, g_FIJ);
    cudaGetSymbolAddress((void**)&OUTM,g_OUTM);

    const float inv = 0.08838834764831845f;   // 1/sqrt(128)
    dim3 thr(256);
    const float* NOB = (const float*)0;
    const float* NOG = (const float*)0;

    // lazily created side streams + fork/join events
    static cudaStream_t s1 = 0, s2 = 0;
    static cudaEvent_t evR = 0, evEr = 0, evNode = 0, evG = 0, evQ1 = 0, evQ2 = 0;
    if (!s1){
        cudaStreamCreateWithFlags(&s1, cudaStreamNonBlocking);
        cudaStreamCreateWithFlags(&s2, cudaStreamNonBlocking);
        cudaEventCreateWithFlags(&evR,   cudaEventDisableTiming);
        cudaEventCreateWithFlags(&evEr,  cudaEventDisableTiming);
        cudaEventCreateWithFlags(&evNode,cudaEventDisableTiming);
        cudaEventCreateWithFlags(&evG,   cudaEventDisableTiming);
        cudaEventCreateWithFlags(&evQ1,  cudaEventDisableTiming);
        cudaEventCreateWithFlags(&evQ2,  cudaEventDisableTiming);
    }

    // ---- fork ----
    cudaEventRecord(evR, 0);
    cudaStreamWaitEvent(s1, evR, 0);
    cudaStreamWaitEvent(s2, evR, 0);

    // s1: er branch  (HB = silu(ea@erW1+b1); TPW = HB@erW2 + b2)
    sgemm_k<1,0><<<dim3(1,rtE,1),  thr, 0, s1>>>(ea,  20, erW1, 128, HB, 128, erb1, 1.f, nE, 128, 20, 0,0, NOG,0);
    sgemm_k<0,0><<<dim3(11,rtE,1), thr, 0, s1>>>(HB, 128, erW2, WN, TPW, WN,  erb2, 1.f, nE, WN, 128, 0,0, NOG,0);
    cudaEventRecord(evEr, s1);

    // s2: w3j + node chain (independent of edges until tp_k)
    init_w3j_k<<<11,128,0,s2>>>();
    permute_in_k<<<nN,128,0,s2>>>(x, XM);
    sgemm_k<0,0><<<dim3(1,rtN,1), thr,0,s2>>>(XM,     NDIM, Wp0, 128, XP,     NDIM, bp0, inv, nN, 128, 128, 0,   0,   NOG,0);
    sgemm_k<0,0><<<dim3(1,rtN,3), thr,0,s2>>>(XM+128, NDIM, Wp1, 128, XP+128, NDIM, NOB, inv, nN, 128, 128, 128, 128, NOG,0);
    sgemm_k<0,0><<<dim3(1,rtN,5), thr,0,s2>>>(XM+512, NDIM, Wp2, 128, XP+512, NDIM, NOB, inv, nN, 128, 128, 128, 128, NOG,0);
    f0_prep_k<<<nN,128,0,s2>>>(XP, F0);
    sgemm_k<1,0><<<dim3(3,rtN,1), thr,0,s2>>>(F0, NIC, ngAW1, NIC, H2, NIC, ngAb1, 1.f, nN, NIC, NIC, 0,0, NOG,0);
    sgemm_k<0,0><<<dim3(3,rtN,1), thr,0,s2>>>(H2, NIC, ngAW2, NIC, G,  NIC, ngAb2, 1.f, nN, NIC, NIC, 0,0, NOG,0);
    gate_k<<<nN,128,0,s2>>>(XP, G);
    cudaEventRecord(evNode, s2);

    // stream 0: es branch
    edge_s0_k<<<nE,128>>>(x, ei, S0, nE);
    sgemm_k<1,0><<<dim3(1,rtE,1),  thr>>>(S0, 512, esW1, 128, H, 128, esb1, 1.f, nE, 128, 512, 0,0, NOG,0);
    cudaStreamWaitEvent(0, evEr, 0);            // join er chain
    sgemm_k<2,0><<<dim3(11,rtE,1), thr>>>(H, 128, esW2, WN, TPW, WN, esb2, 1.f, nE, WN, 128, 0,0, NOG,0);

    // join node chain, then tensor product per edge (also emits F0)
    cudaStreamWaitEvent(0, evNode, 0);
    tp_k<<<nE,128>>>(XP, ei, TPW, FIJ, F0, nE);

    // edge post: norm_gate MLP (gate G; applied via fusion below)
    sgemm_k<1,0><<<dim3(3,rtE,1), thr>>>(F0, NIC, ngBW1, NIC, H2, NIC, ngBb1, 1.f, nE, NIC, NIC, 0,0, NOG,0);
    sgemm_k<0,0><<<dim3(3,rtE,1), thr>>>(H2, NIC, ngBW2, NIC, G,  NIC, ngBb2, 1.f, nE, NIC, NIC, 0,0, NOG,0);
    cudaEventRecord(evG, 0);
    cudaStreamWaitEvent(s1, evG, 0);
    cudaStreamWaitEvent(s2, evG, 0);

    // edge post: o3_linear -> OUTM (m-major); gate fused into A-staging.
    // three independent GEMMs forked across streams to pack tail waves.
    sgemm_k<0,0><<<dim3(1,rtE,1), thr, 0, 0 >>>(G,       NIC,  Wq0, 128, OUTM,     NDIM, NOB, inv, nE, 128, 128, 0,   0,   NOG, 0);
    sgemm_k<0,1><<<dim3(1,rtE,3), thr, 0, s1>>>(FIJ+128, NDIM, Wq1, 128, OUTM+128, NDIM, NOB, inv, nE, 128, 128, 128, 128, G, 128);
    sgemm_k<0,1><<<dim3(1,rtE,5), thr, 0, s2>>>(FIJ+512, NDIM, Wq2, 128, OUTM+512, NDIM, NOB, inv, nE, 128, 128, 128, 128, G, 256);
    cudaEventRecord(evQ1, s1);
    cudaEventRecord(evQ2, s2);
    cudaStreamWaitEvent(0, evQ1, 0);
    cudaStreamWaitEvent(0, evQ2, 0);

    // interleave to reference layout
    permute_out_k<<<nE,128>>>(OUTM, out);
}

// round 16
// speedup vs baseline: 1.2246x; 1.0311x over previous
#include <cuda_runtime.h>
#include <math.h>
#include <stdint.h>

#define NDIM 1152
#define WN   1408
#define NIC  384
#define NN_MAX 10000
#define NE_MAX 50000

// ---------------- static scratch (no allocation allowed) ----------------
__device__ float g_S0  [(size_t)NE_MAX * 512];
__device__ float g_H   [(size_t)NE_MAX * 128];   // es hidden
__device__ float g_HB  [(size_t)NE_MAX * 128];   // er hidden (concurrent)
__device__ float g_TPW [(size_t)NE_MAX * WN];
__device__ float g_XM  [(size_t)NN_MAX * NDIM];  // x permuted to m-major
__device__ float g_XP  [(size_t)NN_MAX * NDIM];  // m-major irrep layout
__device__ float g_F0  [(size_t)NE_MAX * NIC];
__device__ float g_H2  [(size_t)NE_MAX * NIC];
__device__ float g_G   [(size_t)NE_MAX * NIC];
__device__ float g_FIJ [(size_t)NE_MAX * NDIM];  // m-major (ungated)
__device__ float g_OUTM[(size_t)NE_MAX * NDIM];  // m-major (v1/v2 slices only)
__device__ float g_W3J[363];

// ---------------- Wigner 3j init (exact port of reference) --------------
__constant__ int c_l1[11]  = {0,0,0,1,1,1,1,2,2,2,2};
__constant__ int c_l2[11]  = {0,1,2,0,1,1,2,0,1,2,2};
__constant__ int c_l3[11]  = {0,1,2,1,0,2,1,2,1,0,2};
__constant__ int c_off[11] = {0,1,10,35,44,53,98,143,168,213,238};

__device__ double dfact(int n){ double r=1.0; for(int i=2;i<=n;i++) r*=(double)i; return r; }

__device__ double su2cg(int j1,int j2,int j3,int m1,int m2,int m3){
    if (m1+m2 != m3) return 0.0;
    double pref = sqrt((2.0*j3+1.0)*dfact(j1+j2-j3)*dfact(j1-j2+j3)*dfact(-j1+j2+j3)/dfact(j1+j2+j3+1));
    pref *= sqrt(dfact(j3+m3)*dfact(j3-m3)*dfact(j1-m1)*dfact(j1+m1)*dfact(j2-m2)*dfact(j2+m2));
    double s = 0.0;
    for (int k=0;k<=j1+j2-j3;k++){
        int a=j1-m1-k, b=j2+m2-k, c=j3-j2+m1+k, d=j3-j1-m2+k;
        if (a<0||b<0||c<0||d<0) continue;
        double t = 1.0/(dfact(k)*dfact(j1+j2-j3-k)*dfact(a)*dfact(b)*dfact(c)*dfact(d));
        s += (k&1) ? -t : t;
    }
    return pref*s;
}

__device__ void qmat(int l, double* Qr, double* Qi){
    int d = 2*l+1;
    for (int i=0;i<d*d;i++){ Qr[i]=0.0; Qi[i]=0.0; }
    double is2 = 1.0/sqrt(2.0);
    for (int m=-l;m<0;m++){
        Qr[(l+m)*d+(l-m)] = is2;
        Qi[(l+m)*d+(l+m)] = -is2;
    }
    Qr[l*d+l] = 1.0;
    for (int m=1;m<=l;m++){
        double sg = (m&1) ? -1.0 : 1.0;
        Qr[(l+m)*d+(l+m)] = sg*is2;
        Qi[(l+m)*d+(l-m)] = sg*is2;
    }
    if (l==1){ for (int i=0;i<d*d;i++){ double r=Qr[i], im=Qi[i]; Qr[i]=im; Qi[i]=-r; } }
    else if (l==2){ for (int i=0;i<d*d;i++){ Qr[i]=-Qr[i]; Qi[i]=-Qi[i]; } }
}

__global__ void init_w3j_k(){
    int p = blockIdx.x;
    int l1=c_l1[p], l2=c_l2[p], l3=c_l3[p];
    int d1=2*l1+1, d2=2*l2+1, d3=2*l3+1;
    int n = d1*d2*d3;
    __shared__ double Cc[125];
    __shared__ double Q1r[25],Q1i[25],Q2r[25],Q2i[25],Q3r[25],Q3i[25];
    __shared__ double Tr[125], Ti[125];
    int tid = threadIdx.x;
    for (int idx=tid; idx<n; idx+=blockDim.x){
        int a = idx/(d2*d3), b = (idx/d3)%d2, c = idx%d3;
        Cc[idx] = su2cg(l1,l2,l3,a-l1,b-l2,c-l3);
    }
    if (tid==0){ qmat(l1,Q1r,Q1i); qmat(l2,Q2r,Q2i); qmat(l3,Q3r,Q3i); }
    __syncthreads();
    for (int idx=tid; idx<n; idx+=blockDim.x){
        int i = idx/(d2*d3), j = (idx/d3)%d2, k = idx%d3;
        double tre=0.0, tim=0.0;
        for (int a=0;a<d1;a++)
        for (int b=0;b<d2;b++){
            double q1r=Q1r[a*d1+i], q1i=Q1i[a*d1+i];
            double q2r=Q2r[b*d2+j], q2i=Q2i[b*d2+j];
            double q12r = q1r*q2r - q1i*q2i;
            double q12i = q1r*q2i + q1i*q2r;
            for (int c=0;c<d3;c++){
                double cc = Cc[(a*d2+b)*d3+c];
                if (cc==0.0) continue;
                double q3r = Q3r[c*d3+k], q3i = -Q3i[c*d3+k];
                tre += cc*(q12r*q3r - q12i*q3i);
                tim += cc*(q12r*q3i + q12i*q3r);
            }
        }
        Tr[idx]=tre; Ti[idx]=tim;
    }
    __syncthreads();
    if (tid==0){
        double nr=0.0, ni=0.0;
        for (int idx=0;idx<n;idx++){ nr += Tr[idx]*Tr[idx]; ni += Ti[idx]*Ti[idx]; }
        bool ure = (nr >= ni);
        double nn = sqrt(ure ? nr : ni);
        for (int idx=0;idx<n;idx++)
            g_W3J[c_off[p]+idx] = (float)((ure ? Tr[idx] : Ti[idx]) / nn);
    }
}

// ---------------- packed f32x2 helpers -----------------------------------
__device__ __forceinline__ unsigned long long pk2(float lo, float hi){
    unsigned long long r;
    asm("mov.b64 %0, {%1,%2};" : "=l"(r) : "f"(lo), "f"(hi));
    return r;
}
__device__ __forceinline__ void upk2(unsigned long long v, float& lo, float& hi){
    asm("mov.b64 {%0,%1}, %2;" : "=f"(lo), "=f"(hi) : "l"(v));
}
__device__ __forceinline__ unsigned long long ffma2(unsigned long long a,
                                                    unsigned long long b,
                                                    unsigned long long c){
    unsigned long long d;
    asm("fma.rn.f32x2 %0, %1, %2, %3;" : "=l"(d) : "l"(a), "l"(b), "l"(c));
    return d;
}

// ---------------- tiled SGEMM (proven R12 engine: 8-wide k-chunks) -------
// C = epi(alpha*A@B + bias [, *C]).  A row-major (ldaR, contiguous k),
// B row-major K x N (ldb), C row-major (ldcR, col stride 1), N mult of 128.
// Warp tile 32x64 (split 4+4 microtile).  EPI: 0 linear, 1 silu, 2 mult-into-C.
// GATED: A multiplied by Gm[row, goff+k] during staging.
template<int EPI, int GATED>
__global__ __launch_bounds__(256)
void sgemm_k(const float* __restrict__ A, int ldaR,
             const float* __restrict__ B, int ldb,
             float* __restrict__ C, long long ldcR,
             const float* __restrict__ bias, float alpha,
             int M, int N, int K, int zA, int zC,
             const float* __restrict__ Gm, int goff)
{
    __shared__ float As[2][8][132];
    __shared__ float Bs[2][8][132];
    const int bm = blockIdx.y * 128;
    const int bn = blockIdx.x * 128;
    A += (size_t)blockIdx.z * zA;
    C += (size_t)blockIdx.z * zC;
    const int tid  = threadIdx.x;
    const int lane = tid & 31, warp = tid >> 5;
    const int lx = lane & 7,  ly = lane >> 3;
    const int wx = warp & 1,  wy = warp >> 1;
    const int cb = (wx*8 + lx) * 4;
    const int rb = (wy*4 + ly) * 4;
    const int ar = tid >> 1;
    const int ak = (tid & 1) * 4;
    const int bk = tid >> 5;
    const int bj = (tid & 31) * 4;

    unsigned long long acc[8][4];
#pragma unroll
    for (int r=0;r<8;r++)
#pragma unroll
        for (int c=0;c<4;c++) acc[r][c] = pk2(0.f, 0.f);

    const int nc = (K+7)/8;
    float4 va, vb;

    {
        int gar = bm+ar, gk = ak;
        va = make_float4(0.f,0.f,0.f,0.f);
        if (gar < M){
            const float* ap = A + (size_t)gar*ldaR;
            if (gk+3 < K) va = *(const float4*)(ap+gk);
            else {
                if (gk   < K) va.x = ap[gk];
                if (gk+1 < K) va.y = ap[gk+1];
                if (gk+2 < K) va.z = ap[gk+2];
                if (gk+3 < K) va.w = ap[gk+3];
            }
            if (GATED){
                float4 vg = *(const float4*)(Gm + (size_t)gar*NIC + goff + gk);
                va.x *= vg.x; va.y *= vg.y; va.z *= vg.z; va.w *= vg.w;
            }
        }
        vb = make_float4(0.f,0.f,0.f,0.f);
        if (bk < K) vb = *(const float4*)(B + (size_t)bk*ldb + bn + bj);
    }
    As[0][ak  ][ar] = va.x;
    As[0][ak+1][ar] = va.y;
    As[0][ak+2][ar] = va.z;
    As[0][ak+3][ar] = va.w;
    *(float4*)&Bs[0][bk][bj] = vb;
    __syncthreads();

    for (int c=0; c<nc; c++){
        int cur = c & 1;
        if (c+1 < nc){
            int k0 = (c+1)*8;
            int gar = bm+ar, gk = k0+ak;
            va = make_float4(0.f,0.f,0.f,0.f);
            if (gar < M){
                const float* ap = A + (size_t)gar*ldaR;
                if (gk+3 < K) va = *(const float4*)(ap+gk);
                else {
                    if (gk   < K) va.x = ap[gk];
                    if (gk+1 < K) va.y = ap[gk+1];
                    if (gk+2 < K) va.z = ap[gk+2];
                    if (gk+3 < K) va.w = ap[gk+3];
                }
                if (GATED){
                    float4 vg = *(const float4*)(Gm + (size_t)gar*NIC + goff + gk);
                    va.x *= vg.x; va.y *= vg.y; va.z *= vg.z; va.w *= vg.w;
                }
            }
            vb = make_float4(0.f,0.f,0.f,0.f);
            int gbk = k0+bk;
            if (gbk < K) vb = *(const float4*)(B + (size_t)gbk*ldb + bn + bj);
        }
#pragma unroll
        for (int k=0;k<8;k++){
            float4 a0 = *(const float4*)&As[cur][k][rb];
            float4 a1 = *(const float4*)&As[cur][k][rb+64];
            ulonglong2 u0 = *(const ulonglong2*)&Bs[cur][k][cb];
            ulonglong2 u1 = *(const ulonglong2*)&Bs[cur][k][cb+64];
            unsigned long long b2[4] = {u0.x, u0.y, u1.x, u1.y};
            float av[8] = {a0.x,a0.y,a0.z,a0.w,a1.x,a1.y,a1.z,a1.w};
#pragma unroll
            for (int r=0;r<8;r++){
                unsigned long long a2 = pk2(av[r], av[r]);
#pragma unroll
                for (int cc=0;cc<4;cc++)
                    acc[r][cc] = ffma2(a2, b2[cc], acc[r][cc]);
            }
        }
        if (c+1 < nc){
            int nxt = (c+1)&1;
            As[nxt][ak  ][ar] = va.x;
            As[nxt][ak+1][ar] = va.y;
            As[nxt][ak+2][ar] = va.z;
            As[nxt][ak+3][ar] = va.w;
            *(float4*)&Bs[nxt][bk][bj] = vb;
            __syncthreads();
        }
    }

    float bi[8];
#pragma unroll
    for (int c=0;c<8;c++){
        int gj = bn + cb + (c>>2)*64 + (c&3);
        bi[c] = bias ? bias[gj] : 0.f;
    }
#pragma unroll
    for (int r=0;r<8;r++){
        int gi = bm + rb + (r>>2)*64 + (r&3);
        if (gi >= M) continue;
        float v[8];
#pragma unroll
        for (int c=0;c<4;c++) upk2(acc[r][c], v[c*2], v[c*2+1]);
        float* cp0 = C + (long long)gi*ldcR + bn + cb;
        float* cp1 = cp0 + 64;
        if (EPI==2){
            float4 c0 = *(const float4*)cp0;
            float4 c1 = *(const float4*)cp1;
            float cv[8] = {c0.x,c0.y,c0.z,c0.w,c1.x,c1.y,c1.z,c1.w};
#pragma unroll
            for (int c=0;c<8;c++) v[c] = (v[c]*alpha + bi[c]) * cv[c];
        } else {
#pragma unroll
            for (int c=0;c<8;c++){
                float t = v[c]*alpha + bi[c];
                if (EPI==1) t = t / (1.f + __expf(-t));
                v[c] = t;
            }
        }
        *(float4*)cp0 = make_float4(v[0],v[1],v[2],v[3]);
        *(float4*)cp1 = make_float4(v[4],v[5],v[6],v[7]);
    }
}

// ---------------- glue kernels (m-major irrep layout) --------------------
__global__ void edge_s0_k(const float* __restrict__ x, const int* __restrict__ ei,
                          float* __restrict__ S0, int nE){
    int e = blockIdx.x, u = threadIdx.x;
    int s = ei[e], d = ei[nE+e];
    const float* a = x + (size_t)s*NDIM;
    const float* b = x + (size_t)d*NDIM;
    float* o = S0 + (size_t)e*512;
    o[u]      = a[u];
    o[128+u]  = b[u];
    float d1 = 0.f;
#pragma unroll
    for (int m=0;m<3;m++) d1 += a[128+u*3+m]*b[128+u*3+m];
    float d2 = 0.f;
#pragma unroll
    for (int m=0;m<5;m++) d2 += a[512+u*5+m]*b[512+u*5+m];
    o[256+u] = d1*0.57735026918962576f;
    o[384+u] = d2*0.44721359549995794f;
}

// u-major x -> m-major XM
__global__ void permute_in_k(const float* __restrict__ x, float* __restrict__ XM){
    __shared__ float buf[NDIM];
    int n = blockIdx.x, t = threadIdx.x;
    const float* src = x + (size_t)n*NDIM;
    for (int j=t;j<NDIM;j+=128) buf[j] = src[j];
    __syncthreads();
    float* o = XM + (size_t)n*NDIM;
    for (int j=t;j<NDIM;j+=128){
        float v;
        if (j < 128) v = buf[j];
        else if (j < 512){ int r=j-128; int m=r>>7, u=r&127; v = buf[128 + u*3 + m]; }
        else             { int r=j-512; int m=r/128, u=r%128; v = buf[512 + u*5 + m]; }
        o[j] = v;
    }
}

__global__ void f0_prep_k(const float* __restrict__ V, float* __restrict__ F0){
    int n = blockIdx.x, u = threadIdx.x;
    const float* r = V + (size_t)n*NDIM;
    float* o = F0 + (size_t)n*NIC;
    o[u] = r[u];
    float s = 0.f;
#pragma unroll
    for (int m=0;m<3;m++){ float t = r[128+m*128+u]; s += t*t; }
    o[128+u] = sqrtf(s);
    s = 0.f;
#pragma unroll
    for (int m=0;m<5;m++){ float t = r[512+m*128+u]; s += t*t; }
    o[256+u] = sqrtf(s);
}

__global__ void gate_k(float* __restrict__ V, const float* __restrict__ G){
    int n = blockIdx.x, u = threadIdx.x;
    float* r = V + (size_t)n*NDIM;
    const float* g = G + (size_t)n*NIC;
    r[u] = g[u];
    float g1 = g[128+u];
#pragma unroll
    for (int m=0;m<3;m++) r[128+m*128+u] *= g1;
    float g2 = g[256+u];
#pragma unroll
    for (int m=0;m<5;m++) r[512+m*128+u] *= g2;
}

// m-major tensor product; also emits F0 = [o0, |o1|, |o2|]
__global__ void tp_k(const float* __restrict__ XP, const int* __restrict__ ei,
                     const float* __restrict__ TPW, float* __restrict__ FIJ,
                     float* __restrict__ F0, int nE){
    __shared__ float w3[363];
    int e = blockIdx.x, u = threadIdx.x;
    for (int i=u;i<363;i+=128) w3[i] = g_W3J[i];
    __syncthreads();
    int s = ei[e], d = ei[nE+e];
    const float* a = XP + (size_t)s*NDIM;
    const float* b = XP + (size_t)d*NDIM;
    float s1 = a[u], s2 = b[u];
    float v11[3], v12[3], v21[5], v22[5];
#pragma unroll
    for (int m=0;m<3;m++){ v11[m]=a[128+m*128+u]; v12[m]=b[128+m*128+u]; }
#pragma unroll
    for (int m=0;m<5;m++){ v21[m]=a[512+m*128+u]; v22[m]=b[512+m*128+u]; }
    const float* W = TPW + (size_t)e*WN + u;
    const float PW0 = 0.57735026918962576f;
    const float PW1 = 0.86602540378443865f;
    const float PW2 = 1.11803398874989485f;
    float o0 = 0.f, o1[3] = {0,0,0}, o2[5] = {0,0,0,0,0};
    float wp, f, t;

    wp = W[0];
    o0 += PW0*wp*s1*s2*w3[0];
    wp = W[128]; f = PW1*wp*s1;
#pragma unroll
    for (int j=0;j<3;j++){ t = f*v12[j];
#pragma unroll
        for (int k=0;k<3;k++) o1[k] += t*w3[1 + j*3 + k]; }
    wp = W[256]; f = PW2*wp*s1;
#pragma unroll
    for (int j=0;j<5;j++){ t = f*v22[j];
#pragma unroll
        for (int k=0;k<5;k++) o2[k] += t*w3[10 + j*5 + k]; }
    wp = W[384]; f = PW1*wp*s2;
#pragma unroll
    for (int i=0;i<3;i++){ t = f*v11[i];
#pragma unroll
        for (int k=0;k<3;k++) o1[k] += t*w3[35 + i*3 + k]; }
    wp = W[512]; f = PW0*wp;
#pragma unroll
    for (int i=0;i<3;i++)
#pragma unroll
        for (int j=0;j<3;j++) o0 += f*v11[i]*v12[j]*w3[44 + i*3 + j];
    wp = W[640]; f = PW2*wp;
#pragma unroll
    for (int i=0;i<3;i++)
#pragma unroll
        for (int j=0;j<3;j++){ t = f*v11[i]*v12[j];
#pragma unroll
            for (int k=0;k<5;k++) o2[k] += t*w3[53 + (i*3+j)*5 + k]; }
    wp = W[768]; f = PW1*wp;
#pragma unroll
    for (int i=0;i<3;i++)
#pragma unroll
        for (int j=0;j<5;j++){ t = f*v11[i]*v22[j];
#pragma unroll
            for (int k=0;k<3;k++) o1[k] += t*w3[98 + (i*5+j)*3 + k]; }
    wp = W[896]; f = PW2*wp*s2;
#pragma unroll
    for (int i=0;i<5;i++){ t = f*v21[i];
#pragma unroll
        for (int k=0;k<5;k++) o2[k] += t*w3[143 + i*5 + k]; }
    wp = W[1024]; f = PW1*wp;
#pragma unroll
    for (int i=0;i<5;i++)
#pragma unroll
        for (int j=0;j<3;j++){ t = f*v21[i]*v12[j];
#pragma unroll
            for (int k=0;k<3;k++) o1[k] += t*w3[168 + (i*3+j)*3 + k]; }
    wp = W[1152]; f = PW0*wp;
#pragma unroll
    for (int i=0;i<5;i++)
#pragma unroll
        for (int j=0;j<5;j++) o0 += f*v21[i]*v22[j]*w3[213 + i*5 + j];
    wp = W[1280]; f = PW2*wp;
#pragma unroll
    for (int i=0;i<5;i++)
#pragma unroll
        for (int j=0;j<5;j++){ t = f*v21[i]*v22[j];
#pragma unroll
            for (int k=0;k<5;k++) o2[k] += t*w3[238 + (i*5+j)*5 + k]; }

    float* o = FIJ + (size_t)e*NDIM;
    o[u] = o0;
    float n1 = 0.f, n2 = 0.f;
#pragma unroll
    for (int m=0;m<3;m++){ o[128+m*128+u] = o1[m]; n1 += o1[m]*o1[m]; }
#pragma unroll
    for (int m=0;m<5;m++){ o[512+m*128+u] = o2[m]; n2 += o2[m]*o2[m]; }
    float* fo = F0 + (size_t)e*NIC;
    fo[u]       = o0;
    fo[128+u]   = sqrtf(n1);
    fo[256+u]   = sqrtf(n2);
}

// v1 slices m-major -> u-major interleave (cols 128..511 of out)
__global__ void perm_v1_k(const float* __restrict__ OM, float* __restrict__ out){
    __shared__ float buf[384];
    int e = blockIdx.x, t = threadIdx.x;
    const float* src = OM + (size_t)e*NDIM + 128;
#pragma unroll
    for (int i=0;i<3;i++) buf[t + i*128] = src[t + i*128];
    __syncthreads();
    float* o = out + (size_t)e*NDIM + 128;
#pragma unroll
    for (int i=0;i<3;i++){
        int r = t + i*128;                 // 0..383
        o[r] = buf[(r%3)*128 + r/3];
    }
}

// v2 slices m-major -> u-major interleave (cols 512..1151 of out)
__global__ void perm_v2_k(const float* __restrict__ OM, float* __restrict__ out){
    __shared__ float buf[640];
    int e = blockIdx.x, t = threadIdx.x;
    const float* src = OM + (size_t)e*NDIM + 512;
#pragma unroll
    for (int i=0;i<5;i++) buf[t + i*128] = src[t + i*128];
    __syncthreads();
    float* o = out + (size_t)e*NDIM + 512;
#pragma unroll
    for (int i=0;i<5;i++){
        int r = t + i*128;                 // 0..639
        o[r] = buf[(r%5)*128 + r/5];
    }
}

// ---------------- launch --------------------------------------------------
static inline int cdiv(int a, int b){ return (a+b-1)/b; }

extern "C" void kernel_launch(void* const* d_in, const int* in_sizes, int n_in,
                              void* d_out, int out_size)
{
    const float* x     = (const float*)d_in[0];
    const float* ea    = (const float*)d_in[1];
    const int*   ei    = (const int*)  d_in[2];
    const float* Wp0   = (const float*)d_in[3];
    const float* Wp1   = (const float*)d_in[4];
    const float* Wp2   = (const float*)d_in[5];
    const float* bp0   = (const float*)d_in[6];
    const float* ngAW1 = (const float*)d_in[7];
    const float* ngAb1 = (const float*)d_in[8];
    const float* ngAW2 = (const float*)d_in[9];
    const float* ngAb2 = (const float*)d_in[10];
    const float* esW1  = (const float*)d_in[11];
    const float* esb1  = (const float*)d_in[12];
    const float* esW2  = (const float*)d_in[13];
    const float* esb2  = (const float*)d_in[14];
    const float* erW1  = (const float*)d_in[15];
    const float* erb1  = (const float*)d_in[16];
    const float* erW2  = (const float*)d_in[17];
    const float* erb2  = (const float*)d_in[18];
    const float* ngBW1 = (const float*)d_in[19];
    const float* ngBb1 = (const float*)d_in[20];
    const float* ngBW2 = (const float*)d_in[21];
    const float* ngBb2 = (const float*)d_in[22];
    const float* Wq0   = (const float*)d_in[23];
    const float* Wq1   = (const float*)d_in[24];
    const float* Wq2   = (const float*)d_in[25];
    float* out = (float*)d_out;

    int nN = in_sizes[0] / NDIM;
    int nE = in_sizes[2] / 2;
    int rtE = cdiv(nE,128), rtN = cdiv(nN,128);

    float *S0,*H,*HB,*TPW,*XM,*XP,*F0,*H2,*G,*FIJ,*OUTM;
    cudaGetSymbolAddress((void**)&S0,  g_S0);
    cudaGetSymbolAddress((void**)&H,   g_H);
    cudaGetSymbolAddress((void**)&HB,  g_HB);
    cudaGetSymbolAddress((void**)&TPW, g_TPW);
    cudaGetSymbolAddress((void**)&XM,  g_XM);
    cudaGetSymbolAddress((void**)&XP,  g_XP);
    cudaGetSymbolAddress((void**)&F0,  g_F0);
    cudaGetSymbolAddress((void**)&H2,  g_H2);
    cudaGetSymbolAddress((void**)&G,   g_G);
    cudaGetSymbolAddress((void**)&FIJ, g_FIJ);
    cudaGetSymbolAddress((void**)&OUTM,g_OUTM);

    const float inv = 0.08838834764831845f;   // 1/sqrt(128)
    dim3 thr(256);
    const float* NOB = (const float*)0;
    const float* NOG = (const float*)0;

    // lazily created side streams + fork/join events
    static cudaStream_t s1 = 0, s2 = 0;
    static cudaEvent_t evR = 0, evEr = 0, evNode = 0, evG = 0, evQ1 = 0, evQ2 = 0;
    if (!s1){
        cudaStreamCreateWithFlags(&s1, cudaStreamNonBlocking);
        cudaStreamCreateWithFlags(&s2, cudaStreamNonBlocking);
        cudaEventCreateWithFlags(&evR,   cudaEventDisableTiming);
        cudaEventCreateWithFlags(&evEr,  cudaEventDisableTiming);
        cudaEventCreateWithFlags(&evNode,cudaEventDisableTiming);
        cudaEventCreateWithFlags(&evG,   cudaEventDisableTiming);
        cudaEventCreateWithFlags(&evQ1,  cudaEventDisableTiming);
        cudaEventCreateWithFlags(&evQ2,  cudaEventDisableTiming);
    }

    // ---- fork ----
    cudaEventRecord(evR, 0);
    cudaStreamWaitEvent(s1, evR, 0);
    cudaStreamWaitEvent(s2, evR, 0);

    // s1: er branch  (HB = silu(ea@erW1+b1); TPW = HB@erW2 + b2)
    sgemm_k<1,0><<<dim3(1,rtE,1),  thr, 0, s1>>>(ea,  20, erW1, 128, HB, 128, erb1, 1.f, nE, 128, 20, 0,0, NOG,0);
    sgemm_k<0,0><<<dim3(11,rtE,1), thr, 0, s1>>>(HB, 128, erW2, WN, TPW, WN,  erb2, 1.f, nE, WN, 128, 0,0, NOG,0);
    cudaEventRecord(evEr, s1);

    // s2: w3j + node chain (independent of edges until tp_k)
    init_w3j_k<<<11,128,0,s2>>>();
    permute_in_k<<<nN,128,0,s2>>>(x, XM);
    sgemm_k<0,0><<<dim3(1,rtN,1), thr,0,s2>>>(XM,     NDIM, Wp0, 128, XP,     NDIM, bp0, inv, nN, 128, 128, 0,   0,   NOG,0);
    sgemm_k<0,0><<<dim3(1,rtN,3), thr,0,s2>>>(XM+128, NDIM, Wp1, 128, XP+128, NDIM, NOB, inv, nN, 128, 128, 128, 128, NOG,0);
    sgemm_k<0,0><<<dim3(1,rtN,5), thr,0,s2>>>(XM+512, NDIM, Wp2, 128, XP+512, NDIM, NOB, inv, nN, 128, 128, 128, 128, NOG,0);
    f0_prep_k<<<nN,128,0,s2>>>(XP, F0);
    sgemm_k<1,0><<<dim3(3,rtN,1), thr,0,s2>>>(F0, NIC, ngAW1, NIC, H2, NIC, ngAb1, 1.f, nN, NIC, NIC, 0,0, NOG,0);
    sgemm_k<0,0><<<dim3(3,rtN,1), thr,0,s2>>>(H2, NIC, ngAW2, NIC, G,  NIC, ngAb2, 1.f, nN, NIC, NIC, 0,0, NOG,0);
    gate_k<<<nN,128,0,s2>>>(XP, G);
    cudaEventRecord(evNode, s2);

    // stream 0: es branch
    edge_s0_k<<<nE,128>>>(x, ei, S0, nE);
    sgemm_k<1,0><<<dim3(1,rtE,1),  thr>>>(S0, 512, esW1, 128, H, 128, esb1, 1.f, nE, 128, 512, 0,0, NOG,0);
    cudaStreamWaitEvent(0, evEr, 0);            // join er chain
    sgemm_k<2,0><<<dim3(11,rtE,1), thr>>>(H, 128, esW2, WN, TPW, WN, esb2, 1.f, nE, WN, 128, 0,0, NOG,0);

    // join node chain, then tensor product per edge (also emits F0)
    cudaStreamWaitEvent(0, evNode, 0);
    tp_k<<<nE,128>>>(XP, ei, TPW, FIJ, F0, nE);

    // edge post: norm_gate MLP (gate G; applied via fusion below)
    sgemm_k<1,0><<<dim3(3,rtE,1), thr>>>(F0, NIC, ngBW1, NIC, H2, NIC, ngBb1, 1.f, nE, NIC, NIC, 0,0, NOG,0);
    sgemm_k<0,0><<<dim3(3,rtE,1), thr>>>(H2, NIC, ngBW2, NIC, G,  NIC, ngBb2, 1.f, nE, NIC, NIC, 0,0, NOG,0);
    cudaEventRecord(evG, 0);
    cudaStreamWaitEvent(s1, evG, 0);
    cudaStreamWaitEvent(s2, evG, 0);

    // edge post: o3_linear; gate fused into A-staging.  Forked:
    //   stream0: scalar slice -> DIRECTLY into out (same layout, no permute)
    //   s1: v1 slices -> OUTM, then v1 permute
    //   s2: v2 slices -> OUTM, then v2 permute
    sgemm_k<0,0><<<dim3(1,rtE,1), thr, 0, 0 >>>(G,       NIC,  Wq0, 128, out,      NDIM, NOB, inv, nE, 128, 128, 0,   0,   NOG, 0);
    sgemm_k<0,1><<<dim3(1,rtE,3), thr, 0, s1>>>(FIJ+128, NDIM, Wq1, 128, OUTM+128, NDIM, NOB, inv, nE, 128, 128, 128, 128, G, 128);
    perm_v1_k<<<nE,128,0,s1>>>(OUTM, out);
    cudaEventRecord(evQ1, s1);
    sgemm_k<0,1><<<dim3(1,rtE,5), thr, 0, s2>>>(FIJ+512, NDIM, Wq2, 128, OUTM+512, NDIM, NOB, inv, nE, 128, 128, 128, 128, G, 256);
    perm_v2_k<<<nE,128,0,s2>>>(OUTM, out);
    cudaEventRecord(evQ2, s2);

    // join side streams back to origin before capture ends
    cudaStreamWaitEvent(0, evQ1, 0);
    cudaStreamWaitEvent(0, evQ2, 0);
}